// round 11
// baseline (speedup 1.0000x reference)
#include <cuda_runtime.h>

#define B_SZ 1024
#define N_SZ 16
#define T_SZ 256
#define GRID_SZ 256                      // persistent-style: 256 CTAs, all co-resident
#define ITERS (B_SZ / GRID_SZ)           // 4 b-values per CTA, perfectly even
// packed lower-triangular index (compile-time after unroll)
#define TRI(i, j) ((i) * ((i) + 1) / 2 + (j))

// streaming load (zero-reuse data: evict-first policy)
__device__ __forceinline__ float ldcs(const float* p) { return __ldcs(p); }

__global__ void __launch_bounds__(T_SZ, 2)
gll_kernel(const float* __restrict__ pred,
           const float* __restrict__ targ,
           const float* __restrict__ cov,
           float* __restrict__ out) {
    const unsigned t = threadIdx.x;  // 0..255
    float val_acc = 0.0f;

#pragma unroll 1
    for (int it = 0; it < ITERS; it++) {
        // contiguous 256-b band per iteration: co-executing CTAs hit adjacent pages
        const unsigned b = (unsigned)it * GRID_SZ + blockIdx.x;

        // 32-bit indexing: max offset = 1024*16*16*256 = 67M, fits in uint32.
        const unsigned cov_base = b * (N_SZ * N_SZ * T_SZ) + t;

        // ---- load lower triangle of Sigma: cov[b,i,j,t], T innermost => coalesced
        float a[N_SZ * (N_SZ + 1) / 2];
#pragma unroll
        for (int i = 0; i < N_SZ; i++) {
#pragma unroll
            for (int j = 0; j <= i; j++) {
                a[TRI(i, j)] = ldcs(&cov[cov_base + (unsigned)((i * N_SZ + j) * T_SZ)]);
            }
        }

        // ---- in-place Cholesky (left-looking), diagonal stores 1/L_jj.
        // pivots >= 1 (Sigma = A A^T + I): product stays in [1, ~1e26], fp32-safe.
        float pivprod = 1.0f;
#pragma unroll
        for (int j = 0; j < N_SZ; j++) {
            float s = a[TRI(j, j)];
#pragma unroll
            for (int k = 0; k < j; k++) {
                const float l = a[TRI(j, k)];
                s -= l * l;
            }
            pivprod *= s;
            const float inv = rsqrtf(s);
            a[TRI(j, j)] = inv;
#pragma unroll
            for (int i = j + 1; i < N_SZ; i++) {
                float s2 = a[TRI(i, j)];
#pragma unroll
                for (int k = 0; k < j; k++) {
                    s2 -= a[TRI(i, k)] * a[TRI(j, k)];
                }
                a[TRI(i, j)] = s2 * inv;
            }
        }
        const float logdet = __logf(pivprod);

        // ---- diff = pred - target (coalesced), after factorization
        float d[N_SZ];
        const unsigned pt_base = b * (N_SZ * T_SZ) + t;
#pragma unroll
        for (int i = 0; i < N_SZ; i++) {
            const unsigned off = pt_base + (unsigned)(i * T_SZ);
            d[i] = ldcs(&pred[off]) - ldcs(&targ[off]);
        }

        // ---- forward solve L y = diff; quad = ||y||^2 (diagonal holds 1/L_ii)
        float quad = 0.0f;
        float y[N_SZ];
#pragma unroll
        for (int i = 0; i < N_SZ; i++) {
            float s = d[i];
#pragma unroll
            for (int k = 0; k < i; k++) {
                s -= a[TRI(i, k)] * y[k];
            }
            y[i] = s * a[TRI(i, i)];
            quad += y[i] * y[i];
        }

        val_acc += quad + logdet;
    }

    float val = val_acc * (1.0f / ((float)B_SZ * (float)T_SZ));

    // ---- one block reduction at the end: warp shuffle, then smem across 8 warps
#pragma unroll
    for (int off = 16; off > 0; off >>= 1)
        val += __shfl_xor_sync(0xFFFFFFFFu, val, off);

    __shared__ float warp_sums[T_SZ / 32];
    const int lane = threadIdx.x & 31;
    const int wid  = threadIdx.x >> 5;
    if (lane == 0) warp_sums[wid] = val;
    __syncthreads();

    if (wid == 0) {
        float v = (lane < T_SZ / 32) ? warp_sums[lane] : 0.0f;
#pragma unroll
        for (int off = 4; off > 0; off >>= 1)
            v += __shfl_xor_sync(0xFFFFFFFFu, v, off);
        if (lane == 0) atomicAdd(out, v);
    }
}

extern "C" void kernel_launch(void* const* d_in, const int* in_sizes, int n_in,
                              void* d_out, int out_size) {
    const float* pred = (const float*)d_in[0];
    const float* targ = (const float*)d_in[1];
    const float* cov  = (const float*)d_in[2];
    float* out = (float*)d_out;

    // Graph-capturable memset node.
    cudaMemsetAsync(out, 0, sizeof(float));
    gll_kernel<<<GRID_SZ, T_SZ>>>(pred, targ, cov, out);
}